// round 8
// baseline (speedup 1.0000x reference)
#include <cuda_runtime.h>
#include <math.h>
#include <stdint.h>

// Problem constants: B=64, S=2048, I=256, H=256, G=2H=512
#define BATCH 64
#define SEQ   2048
#define HID   256
#define GATES 512
#define WROWS 272          // padded rows in global transposed weights
#define ZROW  256          // all-zero row index (pad)

#define CL    8            // CTAs per cluster
#define NBC   4            // batch elements per cluster
#define NCL   16           // clusters (16*4 = 64 batches)
#define CPC   64           // gate columns per CTA (32 f + 32 c)
#define SROWS 257          // smem weight rows (256 + zero row)

// -------- scratch (static device arrays; no allocation) --------
__device__ float g_gx[67108864];          // (B*S, 512) fp32 = 256 MB
__device__ float g_WhT0[WROWS * GATES];   // [j][g], rows >= 256 are zero
__device__ float g_WiT1[WROWS * GATES];
__device__ float g_WhT1[WROWS * GATES];

// ---------------------------------------------------------------
// Kernel 0: transpose weights into padded [j][g] layout; zero pad rows.
// ---------------------------------------------------------------
__global__ void prep_kernel(const float* __restrict__ Wh0,
                            const float* __restrict__ Wi1,
                            const float* __restrict__ Wh1)
{
    int idx = blockIdx.x * 256 + threadIdx.x;
    const int perp = WROWS * GATES;
    if (idx < 3 * perp) {
        int m = idx / perp;
        int e = idx - m * perp;
        int j = e >> 9;
        int g = e & 511;
        const float* src = (m == 0) ? Wh0 : (m == 1) ? Wi1 : Wh1;
        float*       dst = (m == 0) ? g_WhT0 : (m == 1) ? g_WiT1 : g_WhT1;
        dst[e] = (j < HID) ? src[g * HID + j] : 0.0f;
    }
}

// ---------------------------------------------------------------
// Kernel 1: gx0 = (x @ Wi0^T + bi0) + bh0   (unchanged — passing)
// ---------------------------------------------------------------
__global__ void __launch_bounds__(256, 2)
gemm_gx_kernel(const float* __restrict__ x,
               const float* __restrict__ Wi0,
               const float* __restrict__ bi0,
               const float* __restrict__ bh0)
{
    __shared__ float As[32][68];
    __shared__ float Bs[32][68];

    const int m0  = blockIdx.x * 64;
    const int n0  = blockIdx.y * 64;
    const int tid = threadIdx.x;
    const int tx  = tid & 15;
    const int ty  = tid >> 4;

    float acc[4][4];
#pragma unroll
    for (int i = 0; i < 4; i++)
#pragma unroll
        for (int j = 0; j < 4; j++) acc[i][j] = 0.f;

    for (int k0 = 0; k0 < 256; k0 += 32) {
#pragma unroll
        for (int v = 0; v < 2; v++) {
            int idx = tid + v * 256;
            int r   = idx >> 3;
            int kk  = (idx & 7) << 2;
            float4 av = *reinterpret_cast<const float4*>(
                x + (size_t)(m0 + r) * 256 + (k0 + kk));
            As[kk + 0][r] = av.x; As[kk + 1][r] = av.y;
            As[kk + 2][r] = av.z; As[kk + 3][r] = av.w;
            float4 bv = *reinterpret_cast<const float4*>(
                Wi0 + (size_t)(n0 + r) * 256 + (k0 + kk));
            Bs[kk + 0][r] = bv.x; Bs[kk + 1][r] = bv.y;
            Bs[kk + 2][r] = bv.z; Bs[kk + 3][r] = bv.w;
        }
        __syncthreads();
#pragma unroll
        for (int k = 0; k < 32; k++) {
            float4 av = *reinterpret_cast<const float4*>(&As[k][ty << 2]);
            float4 bv = *reinterpret_cast<const float4*>(&Bs[k][tx << 2]);
            float aa[4] = {av.x, av.y, av.z, av.w};
            float bb[4] = {bv.x, bv.y, bv.z, bv.w};
#pragma unroll
            for (int i = 0; i < 4; i++)
#pragma unroll
                for (int j = 0; j < 4; j++)
                    acc[i][j] = __fmaf_rn(aa[i], bb[j], acc[i][j]);
        }
        __syncthreads();
    }

    float4 b1 = *reinterpret_cast<const float4*>(bi0 + n0 + (tx << 2));
    float4 b2 = *reinterpret_cast<const float4*>(bh0 + n0 + (tx << 2));

#pragma unroll
    for (int i = 0; i < 4; i++) {
        int r = m0 + (ty << 2) + i;
        float4 o;
        o.x = __fadd_rn(__fadd_rn(acc[i][0], b1.x), b2.x);
        o.y = __fadd_rn(__fadd_rn(acc[i][1], b1.y), b2.y);
        o.z = __fadd_rn(__fadd_rn(acc[i][2], b1.z), b2.z);
        o.w = __fadd_rn(__fadd_rn(acc[i][3], b1.w), b2.w);
        *reinterpret_cast<float4*>(g_gx + (size_t)r * GATES + n0 + (tx << 2)) = o;
    }
}

// ---------------------------------------------------------------
// Cluster helpers
// ---------------------------------------------------------------
__device__ __forceinline__ unsigned ctarank()
{
    unsigned r;
    asm("mov.u32 %0, %%cluster_ctarank;" : "=r"(r));
    return r;
}

#define CLUSTER_SYNC() do {                                            \
    asm volatile("barrier.cluster.arrive.aligned;" ::: "memory");      \
    asm volatile("barrier.cluster.wait.aligned;"   ::: "memory");      \
} while (0)

// store 'val' at this smem address in CTA 'rank' of the cluster
__device__ __forceinline__ void remote_st_u32(void* lptr, int rank, unsigned val)
{
    unsigned laddr;
    asm("{ .reg .u64 t; cvta.to.shared.u64 t, %1; cvt.u32.u64 %0, t; }"
        : "=r"(laddr) : "l"(lptr));
    unsigned raddr;
    asm volatile("mapa.shared::cluster.u32 %0, %1, %2;"
                 : "=r"(raddr) : "r"(laddr), "r"(rank));
    asm volatile("st.shared::cluster.u32 [%0], %1;"
                 :: "r"(raddr), "r"(val) : "memory");
}

// XLA logistic: 1/(1+exp(-x)), exp via fp64 rounded to f32 (passing numerics).
__device__ __forceinline__ float sigmoid_ref(float g)
{
    float ef = (float)exp(-(double)g);
    return __fdiv_rn(1.0f, __fadd_rn(1.0f, ef));
}

// ---------------------------------------------------------------
// smem matvec for one gate column: single ascending-j fadd chain over
// the active list (padded to x16 with ZROW -> +0.0f no-ops). Wc points
// at column c (row stride 64 floats). 16-deep LDS batches.
// ---------------------------------------------------------------
__device__ __forceinline__ float matvec_smem(const float* __restrict__ Wc,
                                             const int* __restrict__ lst,
                                             int n16)
{
    float acc = 0.f;
    const int4* l4 = reinterpret_cast<const int4*>(lst);
    const int nb = n16 >> 4;
    for (int k = 0; k < nb; k++) {
        int4 a = l4[k * 4 + 0];
        int4 b = l4[k * 4 + 1];
        int4 c = l4[k * 4 + 2];
        int4 d = l4[k * 4 + 3];
        float w0  = Wc[a.x << 6];
        float w1  = Wc[a.y << 6];
        float w2  = Wc[a.z << 6];
        float w3  = Wc[a.w << 6];
        float w4  = Wc[b.x << 6];
        float w5  = Wc[b.y << 6];
        float w6  = Wc[b.z << 6];
        float w7  = Wc[b.w << 6];
        float w8  = Wc[c.x << 6];
        float w9  = Wc[c.y << 6];
        float w10 = Wc[c.z << 6];
        float w11 = Wc[c.w << 6];
        float w12 = Wc[d.x << 6];
        float w13 = Wc[d.y << 6];
        float w14 = Wc[d.z << 6];
        float w15 = Wc[d.w << 6];
        acc = __fadd_rn(acc, w0);
        acc = __fadd_rn(acc, w1);
        acc = __fadd_rn(acc, w2);
        acc = __fadd_rn(acc, w3);
        acc = __fadd_rn(acc, w4);
        acc = __fadd_rn(acc, w5);
        acc = __fadd_rn(acc, w6);
        acc = __fadd_rn(acc, w7);
        acc = __fadd_rn(acc, w8);
        acc = __fadd_rn(acc, w9);
        acc = __fadd_rn(acc, w10);
        acc = __fadd_rn(acc, w11);
        acc = __fadd_rn(acc, w12);
        acc = __fadd_rn(acc, w13);
        acc = __fadd_rn(acc, w14);
        acc = __fadd_rn(acc, w15);
    }
    return acc;
}

// ---------------- smem byte offsets (dynamic shared) ----------------
#define OFF_W0    0                       // 257*64*4 = 65792
#define OFF_W1    65792
#define OFF_W2    131584
#define OFF_LST0  197376                  // 4*272*4 = 4352
#define OFF_LST1  201728
#define OFF_GSM0  206080                  // 4*64*4 = 1024
#define OFF_MH    207104
#define OFF_GSM1  208128
#define OFF_C0    209152                  // 4*32*4 = 512
#define OFF_C1    209664
#define OFF_MASK0 210176                  // 4*8*4 = 128
#define OFF_MASK1 210304
#define OFF_CNT0  210432                  // 4*4
#define OFF_CNT1  210448
#define SMEM_TOTAL 210464

__device__ __forceinline__ int colmap(int c, int r)
{   // CTA r owns hidden units [32r,32r+32): f-gates 32r+c (c<32), c-gates 256+32r+(c-32)
    return (c < 32) ? (r * 32 + c) : (256 + r * 32 + (c - 32));
}

// ---------------------------------------------------------------
// Kernel 2: clustered spiking-LSTM scan.
// 16 clusters x 8 CTAs; cluster handles 4 batch elements in lockstep.
// Weights live in smem, split by gate columns across the 8 CTAs.
// Per-step cross-CTA traffic: one 32-bit spike mask per CTA per list.
// ---------------------------------------------------------------
__global__ void __launch_bounds__(512, 1) __cluster_dims__(CL, 1, 1)
recurrent_cluster(const float* __restrict__ bi1,
                  const float* __restrict__ bh1,
                  float* __restrict__ out)
{
    extern __shared__ char smem[];
    float*    W0s  = (float*)(smem + OFF_W0);    // Wh0 slice [257][64]
    float*    W1s  = (float*)(smem + OFF_W1);    // Wi1 slice
    float*    W2s  = (float*)(smem + OFF_W2);    // Wh1 slice
    int*      lst0 = (int*)  (smem + OFF_LST0);  // [4][272]
    int*      lst1 = (int*)  (smem + OFF_LST1);
    float*    gsm0 = (float*)(smem + OFF_GSM0);  // [4][64]
    float*    mhsm = (float*)(smem + OFF_MH);
    float*    gsm1 = (float*)(smem + OFF_GSM1);
    float*    c0s  = (float*)(smem + OFF_C0);    // [4][32]
    float*    c1s  = (float*)(smem + OFF_C1);
    unsigned* msk0 = (unsigned*)(smem + OFF_MASK0); // [4][8]
    unsigned* msk1 = (unsigned*)(smem + OFF_MASK1);
    int*      cnt0 = (int*)  (smem + OFF_CNT0);  // [4]
    int*      cnt1 = (int*)  (smem + OFF_CNT1);

    const int tid  = threadIdx.x;
    const int rank = (int)ctarank();
    const int cl   = blockIdx.x >> 3;            // cluster index

    // ---- load weight slices into smem (coalesced from transposed global) ----
    for (int idx = tid; idx < SROWS * CPC; idx += 512) {
        int j = idx >> 6;
        int c = idx & 63;
        int gg = colmap(c, rank);
        W0s[idx] = g_WhT0[j * GATES + gg];
        W1s[idx] = g_WiT1[j * GATES + gg];
        W2s[idx] = g_WhT1[j * GATES + gg];
    }
    if (tid < 128) { c0s[tid] = 0.f; c1s[tid] = 0.f; }
    if (tid < 4)   { cnt0[tid] = 0; cnt1[tid] = 0; }
    __syncthreads();
    CLUSTER_SYNC();

    // ---- per-thread constants ----
    // phase 1 roles: task = tid>>6 in [0,8): q = task>>1, mat = task&1
    const int task = tid >> 6;
    const int tq   = task >> 1;
    const int tmat = task & 1;
    const int c    = tid & 63;
    const int ggc  = colmap(c, rank);

    // phase 2 biases (threads < 256)
    float bi1v = 0.f, bh1v = 0.f;
    if (tid < 256) { bi1v = bi1[ggc]; bh1v = bh1[ggc]; }

    // gx pointer for Wh0 threads (mat==0): batch b = cl*4+tq, gate ggc
    const float* gx_p = g_gx + ((size_t)(cl * NBC + tq) * SEQ) * GATES + ggc;

    // update-role constants (threads < 128): q = tid>>5, l = tid&31
    const int uq = tid >> 5;
    const int ul = tid & 31;
    const int ub = cl * NBC + uq;                // global batch
    const int ui = rank * 32 + ul;               // global hidden unit

    for (int t = 0; t < SEQ; ++t) {
        // ---------------- phase 1: Wh0 (even tasks) || Wh1 (odd tasks) ------
        {
            if (tmat == 0) {
                float gx = __ldcg(gx_p + (size_t)t * GATES);
                float m  = matvec_smem(W0s + c, lst0 + tq * WROWS, cnt0[tq]);
                gsm0[tq * 64 + c] = __fadd_rn(gx, m);     // g_t + h@Wh0^T
            } else {
                float m  = matvec_smem(W2s + c, lst1 + tq * WROWS, cnt1[tq]);
                mhsm[tq * 64 + c] = m;
            }
        }
        __syncthreads();

        // ---------------- L0 update: 32 units x 4 batches ----------------
        if (tid < 128) {
            float f  = sigmoid_ref(gsm0[uq * 64 + ul]);
            float ct = gsm0[uq * 64 + 32 + ul];
            float cc = __fadd_rn(__fmul_rn(f, c0s[tid]),
                                 __fmul_rn(__fsub_rn(1.0f, f), ct));
            c0s[tid] = cc;
            unsigned bal = __ballot_sync(0xffffffffu, cc > 0.f);
            if (ul < CL)                                   // lanes 0..7 -> peers
                remote_st_u32(&msk0[uq * 8 + rank], ul, bal);
        }
        CLUSTER_SYNC();                                    // masks0 delivered

        // ---------------- build lst0 (ascending j, ZROW padded) ----------
#pragma unroll
        for (int it = 0; it < 2; ++it) {
            int idx = tid + it * 512;                      // 0..1023
            int q = idx >> 8, j = idx & 255;
            int pre = 0, tot = 0;
            unsigned mw = 0;
#pragma unroll
            for (int w = 0; w < 8; w++) {
                unsigned mm = msk0[q * 8 + w];
                tot += __popc(mm);
                if (w < (j >> 5)) pre += __popc(mm);
                else if (w == (j >> 5)) {
                    mw = mm;
                    pre += __popc(mm & ((1u << (j & 31)) - 1u));
                }
            }
            int n16 = (tot + 15) & ~15;
            if ((mw >> (j & 31)) & 1u) lst0[q * WROWS + pre] = j;
            if (j < 16 && tot + j < n16) lst0[q * WROWS + tot + j] = ZROW;
            if (j == 0) cnt0[q] = n16;
        }
        __syncthreads();

        // ---------------- phase 2: Wi1 over new h0 -----------------------
        if (tid < 256) {
            int q = tid >> 6;
            float mi = matvec_smem(W1s + c, lst0 + q * WROWS, cnt0[q]);
            float gi = __fadd_rn(__fadd_rn(mi, bi1v), bh1v);
            gsm1[q * 64 + c] = __fadd_rn(gi, mhsm[q * 64 + c]);
        }
        __syncthreads();

        // ---------------- L1 update + output -----------------------------
        if (tid < 128) {
            float f  = sigmoid_ref(gsm1[uq * 64 + ul]);
            float ct = gsm1[uq * 64 + 32 + ul];
            float cc = __fadd_rn(__fmul_rn(f, c1s[tid]),
                                 __fmul_rn(__fsub_rn(1.0f, f), ct));
            c1s[tid] = cc;
            float h  = (cc > 0.f) ? 1.f : 0.f;
            out[((size_t)ub * SEQ + t) * HID + ui] = h;
            unsigned bal = __ballot_sync(0xffffffffu, cc > 0.f);
            if (ul < CL)
                remote_st_u32(&msk1[uq * 8 + rank], ul, bal);
        }
        CLUSTER_SYNC();                                    // masks1 delivered

        // ---------------- build lst1 -------------------------------------
#pragma unroll
        for (int it = 0; it < 2; ++it) {
            int idx = tid + it * 512;
            int q = idx >> 8, j = idx & 255;
            int pre = 0, tot = 0;
            unsigned mw = 0;
#pragma unroll
            for (int w = 0; w < 8; w++) {
                unsigned mm = msk1[q * 8 + w];
                tot += __popc(mm);
                if (w < (j >> 5)) pre += __popc(mm);
                else if (w == (j >> 5)) {
                    mw = mm;
                    pre += __popc(mm & ((1u << (j & 31)) - 1u));
                }
            }
            int n16 = (tot + 15) & ~15;
            if ((mw >> (j & 31)) & 1u) lst1[q * WROWS + pre] = j;
            if (j < 16 && tot + j < n16) lst1[q * WROWS + tot + j] = ZROW;
            if (j == 0) cnt1[q] = n16;
        }
        __syncthreads();
    }

    // finals: h_n (2,B,H) then c_n (2,B,H) after the (B,S,H) output
    if (tid < 128) {
        const size_t HN = (size_t)BATCH * SEQ * HID;
        const size_t CN = HN + (size_t)2 * BATCH * HID;
        float cc0 = c0s[tid], cc1 = c1s[tid];
        out[HN + ((size_t)0 * BATCH + ub) * HID + ui] = (cc0 > 0.f) ? 1.f : 0.f;
        out[HN + ((size_t)1 * BATCH + ub) * HID + ui] = (cc1 > 0.f) ? 1.f : 0.f;
        out[CN + ((size_t)0 * BATCH + ub) * HID + ui] = cc0;
        out[CN + ((size_t)1 * BATCH + ub) * HID + ui] = cc1;
    }
}

// ---------------------------------------------------------------
extern "C" void kernel_launch(void* const* d_in, const int* in_sizes, int n_in,
                              void* d_out, int out_size)
{
    const float* x   = (const float*)d_in[0];
    const float* Wi0 = (const float*)d_in[1];
    const float* bi0 = (const float*)d_in[2];
    const float* Wh0 = (const float*)d_in[3];
    const float* bh0 = (const float*)d_in[4];
    const float* Wi1 = (const float*)d_in[5];
    const float* bi1 = (const float*)d_in[6];
    const float* Wh1 = (const float*)d_in[7];
    const float* bh1 = (const float*)d_in[8];
    float* out = (float*)d_out;

    cudaFuncSetAttribute(recurrent_cluster,
                         cudaFuncAttributeMaxDynamicSharedMemorySize, SMEM_TOTAL);

    prep_kernel<<<1632, 256>>>(Wh0, Wi1, Wh1);

    dim3 gg(2048, 8);
    gemm_gx_kernel<<<gg, 256>>>(x, Wi0, bi0, bh0);

    recurrent_cluster<<<NCL * CL, 512, SMEM_TOTAL>>>(bi1, bh1, out);
}

// round 9
// speedup vs baseline: 2.0329x; 2.0329x over previous
#include <cuda_runtime.h>
#include <math.h>
#include <stdint.h>

// Problem constants: B=64, S=2048, I=256, H=256, G=2H=512
#define BATCH 64
#define SEQ   2048
#define HID   256
#define GATES 512
#define WROWS 272          // 256 real rows + 16 zero pad rows
#define ZROW  256          // index of a guaranteed all-zero row

// -------- scratch (static device arrays; no allocation) --------
__device__ float g_gx[67108864];          // (B*S, 512) fp32 = 256 MB
__device__ float g_WhT0[WROWS * GATES];   // [j][g], rows >= 256 are zero
__device__ float g_WiT1[WROWS * GATES];
__device__ float g_WhT1[WROWS * GATES];

// ---------------------------------------------------------------
// Kernel 0: transpose weights into padded [j][g] layout; zero pad rows.
// ---------------------------------------------------------------
__global__ void prep_kernel(const float* __restrict__ Wh0,
                            const float* __restrict__ Wi1,
                            const float* __restrict__ Wh1)
{
    int idx = blockIdx.x * 256 + threadIdx.x;
    const int perp = WROWS * GATES;
    if (idx < 3 * perp) {
        int m = idx / perp;
        int e = idx - m * perp;
        int j = e >> 9;
        int g = e & 511;
        const float* src = (m == 0) ? Wh0 : (m == 1) ? Wi1 : Wh1;
        float*       dst = (m == 0) ? g_WhT0 : (m == 1) ? g_WiT1 : g_WhT1;
        dst[e] = (j < HID) ? src[g * HID + j] : 0.0f;
    }
}

// ---------------------------------------------------------------
// Kernel 1: gx0 = (x @ Wi0^T + bi0) + bh0   (unchanged — passing)
// ---------------------------------------------------------------
__global__ void __launch_bounds__(256, 2)
gemm_gx_kernel(const float* __restrict__ x,
               const float* __restrict__ Wi0,
               const float* __restrict__ bi0,
               const float* __restrict__ bh0)
{
    __shared__ float As[32][68];
    __shared__ float Bs[32][68];

    const int m0  = blockIdx.x * 64;
    const int n0  = blockIdx.y * 64;
    const int tid = threadIdx.x;
    const int tx  = tid & 15;
    const int ty  = tid >> 4;

    float acc[4][4];
#pragma unroll
    for (int i = 0; i < 4; i++)
#pragma unroll
        for (int j = 0; j < 4; j++) acc[i][j] = 0.f;

    for (int k0 = 0; k0 < 256; k0 += 32) {
#pragma unroll
        for (int v = 0; v < 2; v++) {
            int idx = tid + v * 256;
            int r   = idx >> 3;
            int kk  = (idx & 7) << 2;
            float4 av = *reinterpret_cast<const float4*>(
                x + (size_t)(m0 + r) * 256 + (k0 + kk));
            As[kk + 0][r] = av.x; As[kk + 1][r] = av.y;
            As[kk + 2][r] = av.z; As[kk + 3][r] = av.w;
            float4 bv = *reinterpret_cast<const float4*>(
                Wi0 + (size_t)(n0 + r) * 256 + (k0 + kk));
            Bs[kk + 0][r] = bv.x; Bs[kk + 1][r] = bv.y;
            Bs[kk + 2][r] = bv.z; Bs[kk + 3][r] = bv.w;
        }
        __syncthreads();
#pragma unroll
        for (int k = 0; k < 32; k++) {
            float4 av = *reinterpret_cast<const float4*>(&As[k][ty << 2]);
            float4 bv = *reinterpret_cast<const float4*>(&Bs[k][tx << 2]);
            float aa[4] = {av.x, av.y, av.z, av.w};
            float bb[4] = {bv.x, bv.y, bv.z, bv.w};
#pragma unroll
            for (int i = 0; i < 4; i++)
#pragma unroll
                for (int j = 0; j < 4; j++)
                    acc[i][j] = __fmaf_rn(aa[i], bb[j], acc[i][j]);
        }
        __syncthreads();
    }

    float4 b1 = *reinterpret_cast<const float4*>(bi0 + n0 + (tx << 2));
    float4 b2 = *reinterpret_cast<const float4*>(bh0 + n0 + (tx << 2));

#pragma unroll
    for (int i = 0; i < 4; i++) {
        int r = m0 + (ty << 2) + i;
        float4 o;
        o.x = __fadd_rn(__fadd_rn(acc[i][0], b1.x), b2.x);
        o.y = __fadd_rn(__fadd_rn(acc[i][1], b1.y), b2.y);
        o.z = __fadd_rn(__fadd_rn(acc[i][2], b1.z), b2.z);
        o.w = __fadd_rn(__fadd_rn(acc[i][3], b1.w), b2.w);
        *reinterpret_cast<float4*>(g_gx + (size_t)r * GATES + n0 + (tx << 2)) = o;
    }
}

// ---------------------------------------------------------------
// Cluster helpers (2-CTA clusters)
// ---------------------------------------------------------------
__device__ __forceinline__ unsigned ctarank()
{
    unsigned r;
    asm("mov.u32 %0, %%cluster_ctarank;" : "=r"(r));
    return r;
}

#define CLUSTER_SYNC() do {                                            \
    asm volatile("barrier.cluster.arrive.aligned;" ::: "memory");      \
    asm volatile("barrier.cluster.wait.aligned;"   ::: "memory");      \
} while (0)

__device__ __forceinline__ void remote_st_u32(void* lptr, int rank, unsigned val)
{
    unsigned laddr;
    asm("{ .reg .u64 t; cvta.to.shared.u64 t, %1; cvt.u32.u64 %0, t; }"
        : "=r"(laddr) : "l"(lptr));
    unsigned raddr;
    asm volatile("mapa.shared::cluster.u32 %0, %1, %2;"
                 : "=r"(raddr) : "r"(laddr), "r"(rank));
    asm volatile("st.shared::cluster.u32 [%0], %1;"
                 :: "r"(raddr), "r"(val) : "memory");
}

// XLA logistic: 1/(1+exp(-x)), exp via fp64 rounded to f32 (passing numerics).
__device__ __forceinline__ float sigmoid_ref(float g)
{
    float ef = (float)exp(-(double)g);
    return __fdiv_rn(1.0f, __fadd_rn(1.0f, ef));
}

// ---------------------------------------------------------------
// Scalar active-row sum for one gate column from L2-resident weights.
// Single ascending-j fadd chain; list padded to x16 with ZROW (zero row)
// -> +0.0f no-ops, bit-identical to dense ascending FMA dot w/ binary h.
// 16 independent LDG per batch -> MLP=16, no predication.
// ---------------------------------------------------------------
__device__ __forceinline__ float matvec_col(const float* __restrict__ Wg,
                                            const int* __restrict__ lst,
                                            int n16)
{
    float acc = 0.f;
    const int4* l4 = reinterpret_cast<const int4*>(lst);
    int nb = n16 >> 4;
    for (int k = 0; k < nb; k++) {
        int4 a = l4[k * 4 + 0];
        int4 b = l4[k * 4 + 1];
        int4 c = l4[k * 4 + 2];
        int4 d = l4[k * 4 + 3];
        float w0  = __ldg(Wg + (a.x << 9));
        float w1  = __ldg(Wg + (a.y << 9));
        float w2  = __ldg(Wg + (a.z << 9));
        float w3  = __ldg(Wg + (a.w << 9));
        float w4  = __ldg(Wg + (b.x << 9));
        float w5  = __ldg(Wg + (b.y << 9));
        float w6  = __ldg(Wg + (b.z << 9));
        float w7  = __ldg(Wg + (b.w << 9));
        float w8  = __ldg(Wg + (c.x << 9));
        float w9  = __ldg(Wg + (c.y << 9));
        float w10 = __ldg(Wg + (c.z << 9));
        float w11 = __ldg(Wg + (c.w << 9));
        float w12 = __ldg(Wg + (d.x << 9));
        float w13 = __ldg(Wg + (d.y << 9));
        float w14 = __ldg(Wg + (d.z << 9));
        float w15 = __ldg(Wg + (d.w << 9));
        acc = __fadd_rn(acc, w0);
        acc = __fadd_rn(acc, w1);
        acc = __fadd_rn(acc, w2);
        acc = __fadd_rn(acc, w3);
        acc = __fadd_rn(acc, w4);
        acc = __fadd_rn(acc, w5);
        acc = __fadd_rn(acc, w6);
        acc = __fadd_rn(acc, w7);
        acc = __fadd_rn(acc, w8);
        acc = __fadd_rn(acc, w9);
        acc = __fadd_rn(acc, w10);
        acc = __fadd_rn(acc, w11);
        acc = __fadd_rn(acc, w12);
        acc = __fadd_rn(acc, w13);
        acc = __fadd_rn(acc, w14);
        acc = __fadd_rn(acc, w15);
    }
    return acc;
}

// ---------------------------------------------------------------
// Kernel 2: spiking-LSTM scan. 64 clusters x 2 CTAs (128 CTAs).
// CTA rank r owns hidden units [128r, 128r+128) -> gate columns
// {128r..128r+127} (f) and {256+128r..} (c-tilde). Weights stay in L2.
// Pipelined: Wh0.h0(t) is computed in phase 2 of step t for step t+1.
//   phase 1: warps 8-15: mh = Wh1.h1(t-1)   ||  warps 0-3: L0 update
//   (mask exchange, cluster sync, build lst0)
//   phase 2: warps 0-7: mi = Wi1.h0(t)      ||  warps 8-15: m0' = Wh0.h0(t)
//   L1 update, mask exchange, cluster sync, build lst1.
// ---------------------------------------------------------------
__global__ void __launch_bounds__(512, 1) __cluster_dims__(2, 1, 1)
recurrent2(const float* __restrict__ bi1,
           const float* __restrict__ bh1,
           float* __restrict__ out)
{
    const int tid  = threadIdx.x;
    const int lane = tid & 31;
    const int warp = tid >> 5;
    const int rank = (int)ctarank();
    const int b    = blockIdx.x >> 1;

    __shared__ float m0s[256];     // Wh0 . h0 (precomputed, local cols)
    __shared__ float mhs[256];     // Wh1 . h1(t-1)
    __shared__ float g1s[256];     // layer-1 gates (local cols)
    __shared__ float c0s[128], c1s[128];
    __shared__ alignas(16) int lst0[WROWS], lst1[WROWS];
    __shared__ unsigned msk0[8], msk1[8];
    __shared__ int n0s, n1s;

    // local column k -> global gate index
    const int k256 = tid & 255;
    const int ggc  = (k256 < 128) ? (rank * 128 + k256)
                                  : (256 + rank * 128 + (k256 - 128));

    if (tid < 256) m0s[tid] = 0.f;
    if (tid < 128) { c0s[tid] = 0.f; c1s[tid] = 0.f; }
    if (tid == 0)  { n0s = 0; n1s = 0; }

    float bi1v = 0.f, bh1v = 0.f;
    if (tid < 256) { bi1v = bi1[ggc]; bh1v = bh1[ggc]; }
    __syncthreads();

    const float* gxb = g_gx + (size_t)b * ((size_t)SEQ * GATES);
    const int ubase  = rank * 128;            // first owned hidden unit

    for (int t = 0; t < SEQ; ++t) {
        // ---------------- phase 1 ----------------
        if (tid >= 256) {
            // mh = Wh1 . h1(t-1) for local column k256
            mhs[k256] = matvec_col(g_WhT1 + ggc, lst1, n1s);
        } else if (tid < 128) {
            // L0 update for unit ubase+tid: gates = gx + m0 (precomputed)
            float gxf = __ldcg(gxb + (size_t)t * GATES + (ubase + tid));
            float gxc = __ldcg(gxb + (size_t)t * GATES + (256 + ubase + tid));
            float g  = __fadd_rn(gxf, m0s[tid]);
            float f  = sigmoid_ref(g);
            float ct = __fadd_rn(gxc, m0s[128 + tid]);
            float cc = __fadd_rn(__fmul_rn(f, c0s[tid]),
                                 __fmul_rn(__fsub_rn(1.0f, f), ct));
            c0s[tid] = cc;
            unsigned bal = __ballot_sync(0xffffffffu, cc > 0.f);
            if (lane == 0) {
                msk0[4 * rank + warp] = bal;
                remote_st_u32(&msk0[4 * rank + warp], rank ^ 1, bal);
            }
        }
        CLUSTER_SYNC();                       // masks + mhs visible

        // ---------------- build lst0 (ascending, ZROW padded) -------------
        if (tid < 256) {
            int j = tid, pre = 0, tot = 0;
            unsigned mw = 0;
#pragma unroll
            for (int w = 0; w < 8; w++) {
                unsigned mm = msk0[w];
                tot += __popc(mm);
                if (w < (j >> 5)) pre += __popc(mm);
                else if (w == (j >> 5)) {
                    mw = mm;
                    pre += __popc(mm & ((1u << (j & 31)) - 1u));
                }
            }
            int n16 = (tot + 15) & ~15;
            if ((mw >> (j & 31)) & 1u) lst0[pre] = j;
            if (j < 16 && tot + j < n16) lst0[tot + j] = ZROW;
            if (j == 0) n0s = n16;
        }
        __syncthreads();

        // ---------------- phase 2 ----------------
        if (tid < 256) {
            // gates1 = ((Wi1.h0 + bi1) + bh1) + Wh1.h1
            float mi = matvec_col(g_WiT1 + ggc, lst0, n0s);
            float gi = __fadd_rn(__fadd_rn(mi, bi1v), bh1v);
            g1s[k256] = __fadd_rn(gi, mhs[k256]);
        } else {
            // precompute m0' = Wh0 . h0(t) for next step's L0 update
            m0s[k256] = matvec_col(g_WhT0 + ggc, lst0, n0s);
        }
        __syncthreads();

        // ---------------- L1 update + output ------------------------------
        if (tid < 128) {
            float f  = sigmoid_ref(g1s[tid]);
            float ct = g1s[128 + tid];
            float cc = __fadd_rn(__fmul_rn(f, c1s[tid]),
                                 __fmul_rn(__fsub_rn(1.0f, f), ct));
            c1s[tid] = cc;
            float h  = (cc > 0.f) ? 1.f : 0.f;
            out[((size_t)b * SEQ + t) * HID + (ubase + tid)] = h;
            unsigned bal = __ballot_sync(0xffffffffu, cc > 0.f);
            if (lane == 0) {
                msk1[4 * rank + warp] = bal;
                remote_st_u32(&msk1[4 * rank + warp], rank ^ 1, bal);
            }
        }
        CLUSTER_SYNC();                       // masks1 visible

        // ---------------- build lst1 --------------------------------------
        if (tid < 256) {
            int j = tid, pre = 0, tot = 0;
            unsigned mw = 0;
#pragma unroll
            for (int w = 0; w < 8; w++) {
                unsigned mm = msk1[w];
                tot += __popc(mm);
                if (w < (j >> 5)) pre += __popc(mm);
                else if (w == (j >> 5)) {
                    mw = mm;
                    pre += __popc(mm & ((1u << (j & 31)) - 1u));
                }
            }
            int n16 = (tot + 15) & ~15;
            if ((mw >> (j & 31)) & 1u) lst1[pre] = j;
            if (j < 16 && tot + j < n16) lst1[tot + j] = ZROW;
            if (j == 0) n1s = n16;
        }
        __syncthreads();
    }

    // finals: h_n (2,B,H) then c_n (2,B,H) after the (B,S,H) output
    if (tid < 128) {
        const size_t HN = (size_t)BATCH * SEQ * HID;
        const size_t CN = HN + (size_t)2 * BATCH * HID;
        const int ui = ubase + tid;
        float cc0 = c0s[tid], cc1 = c1s[tid];
        out[HN + ((size_t)0 * BATCH + b) * HID + ui] = (cc0 > 0.f) ? 1.f : 0.f;
        out[HN + ((size_t)1 * BATCH + b) * HID + ui] = (cc1 > 0.f) ? 1.f : 0.f;
        out[CN + ((size_t)0 * BATCH + b) * HID + ui] = cc0;
        out[CN + ((size_t)1 * BATCH + b) * HID + ui] = cc1;
    }
}

// ---------------------------------------------------------------
extern "C" void kernel_launch(void* const* d_in, const int* in_sizes, int n_in,
                              void* d_out, int out_size)
{
    const float* x   = (const float*)d_in[0];
    const float* Wi0 = (const float*)d_in[1];
    const float* bi0 = (const float*)d_in[2];
    const float* Wh0 = (const float*)d_in[3];
    const float* bh0 = (const float*)d_in[4];
    const float* Wi1 = (const float*)d_in[5];
    const float* bi1 = (const float*)d_in[6];
    const float* Wh1 = (const float*)d_in[7];
    const float* bh1 = (const float*)d_in[8];
    float* out = (float*)d_out;

    prep_kernel<<<1632, 256>>>(Wh0, Wi1, Wh1);

    dim3 gg(2048, 8);
    gemm_gx_kernel<<<gg, 256>>>(x, Wi0, bi0, bh0);

    recurrent2<<<BATCH * 2, 512>>>(bi1, bh1, out);
}